// round 5
// baseline (speedup 1.0000x reference)
#include <cuda_runtime.h>

#define NOUT 48
#define CIN 384
#define NPIX 35200       // ny*nx = 200*176 (multiple of 4)
#define NB 4
#define TOTAL_PIX (NB * NPIX)   // 140800 = 550 * 256
#define PF 4             // prefetch pipeline depth

typedef unsigned long long u64;

// ---- packed f32x2 helpers (sm_103a) ----
__device__ __forceinline__ u64 pack2(float lo, float hi) {
    u64 r;
    asm("mov.b64 %0, {%1, %2};" : "=l"(r) : "f"(lo), "f"(hi));
    return r;
}
__device__ __forceinline__ void unpack2(u64 v, float& lo, float& hi) {
    asm("mov.b64 {%0, %1}, %2;" : "=f"(lo), "=f"(hi) : "l"(v));
}
__device__ __forceinline__ void ffma2(u64& d, u64 a, u64 b) {
    asm("fma.rn.f32x2 %0, %1, %2, %0;" : "+l"(d) : "l"(a), "l"(b));
}

extern __shared__ float s_buf[];   // ws[CIN][48] transposed weights, then bs[48]

__device__ __forceinline__ void fma_step(u64 acc[4][12], const float4 f4,
                                         const float* wrow /* ws + 24*ty + c*48 */)
{
    const u64 fA = pack2(f4.x, f4.x);
    const u64 fB = pack2(f4.y, f4.y);
    const u64 fC = pack2(f4.z, f4.z);
    const u64 fD = pack2(f4.w, f4.w);
    const ulonglong2* wr = (const ulonglong2*)wrow;   // 6x LDS.128 broadcast
#pragma unroll
    for (int qq = 0; qq < 6; qq++) {
        const ulonglong2 w2 = wr[qq];
        ffma2(acc[0][2 * qq + 0], fA, w2.x);
        ffma2(acc[0][2 * qq + 1], fA, w2.y);
        ffma2(acc[1][2 * qq + 0], fB, w2.x);
        ffma2(acc[1][2 * qq + 1], fB, w2.y);
        ffma2(acc[2][2 * qq + 0], fC, w2.x);
        ffma2(acc[2][2 * qq + 1], fC, w2.y);
        ffma2(acc[3][2 * qq + 0], fD, w2.x);
        ffma2(acc[3][2 * qq + 1], fD, w2.y);
    }
}

__global__ __launch_bounds__(128, 3)
void proposal_kernel(const float* __restrict__ feat,
                     const float* __restrict__ Wc,
                     const float* __restrict__ bc,
                     const float* __restrict__ Wr,
                     const float* __restrict__ br,
                     float* __restrict__ out)
{
    float* ws = s_buf;               // ws[c*48 + o] = W[o][c]
    float* bs = s_buf + CIN * NOUT;

    const int tid = threadIdx.x;

    for (int i = tid; i < CIN * NOUT; i += blockDim.x) {
        const int c = i / NOUT;
        const int o = i % NOUT;
        ws[i] = (o < 6) ? Wc[o * CIN + c] : Wr[(o - 6) * CIN + c];
    }
    if (tid < NOUT) bs[tid] = (tid < 6) ? bc[tid] : br[tid - 6];
    __syncthreads();

    // 4 warps: (pixel-group pg 0..1) x (output-half ty 0..1)
    const int lane = tid & 31;
    const int warp = tid >> 5;
    const int ty   = warp & 1;        // outputs [24*ty, 24*ty+24)
    const int pg   = warp >> 1;       // pixel sub-tile

    const int g0 = blockIdx.x * 256 + pg * 128 + lane * 4;  // 4 consecutive pixels
    const int b  = g0 / NPIX;         // never crosses batch (NPIX%4==0)
    const int p0 = g0 % NPIX;

    // acc[pix][qp]: outputs (24*ty + 2*qp, +1) packed f32x2
    u64 acc[4][12];
#pragma unroll
    for (int qp = 0; qp < 12; qp++) {
        const u64 bq = pack2(bs[24 * ty + 2 * qp], bs[24 * ty + 2 * qp + 1]);
#pragma unroll
        for (int px = 0; px < 4; px++) acc[px][qp] = bq;
    }

    const float* fb    = feat + (long)b * CIN * NPIX + p0;
    const float* wbase = ws + 24 * ty;

    // ---- software pipeline: PF-deep rotating feature prefetch ----
    float4 buf[PF];
#pragma unroll
    for (int i = 0; i < PF; i++)
        buf[i] = *(const float4*)(fb + (long)i * NPIX);          // LDG.128

#pragma unroll 4
    for (int c = 0; c < CIN - PF; c++) {
        const float4 f4 = buf[c & (PF - 1)];
        buf[c & (PF - 1)] = *(const float4*)(fb + (long)(c + PF) * NPIX);  // prefetch c+PF
        fma_step(acc, f4, wbase + c * NOUT);
    }
#pragma unroll
    for (int c = CIN - PF; c < CIN; c++) {                        // drain
        fma_step(acc, buf[c & (PF - 1)], wbase + c * NOUT);
    }

    // ================= epilogue (validated in R4) =================
    if (ty == 0) {
        // cls: out[(b*6 + o)*NPIX + p], 4 adjacent pixels -> float4 stores
#pragma unroll
        for (int q = 0; q < 3; q++) {
            float lo0, hi0, lo1, hi1, lo2, hi2, lo3, hi3;
            unpack2(acc[0][q], lo0, hi0);
            unpack2(acc[1][q], lo1, hi1);
            unpack2(acc[2][q], lo2, hi2);
            unpack2(acc[3][q], lo3, hi3);
            *(float4*)(out + ((long)b * 6 + 2 * q + 0) * NPIX + p0) =
                make_float4(lo0, lo1, lo2, lo3);
            *(float4*)(out + ((long)b * 6 + 2 * q + 1) * NPIX + p0) =
                make_float4(hi0, hi1, hi2, hi3);
        }
    }

    // reg: layout (B, 3, 2, ny, nx, 7); pair Q=12*ty+j -> r=Q-3, c3=r/7, d=r%7
    float* outr = out + (long)NB * 6 * NPIX;
#pragma unroll
    for (int j = 0; j < 12; j++) {
        const int Q = 12 * ty + j;
        if (Q < 3) continue;                 // compile-time pruned for ty==0
        const int r  = Q - 3;
        const int c3 = r / 7;
        const int d  = r % 7;
        const long base0 = ((((long)b * 3 + c3) * 2 + 0) * NPIX + p0) * 7 + d;  // y=0
        const long base1 = ((((long)b * 3 + c3) * 2 + 1) * NPIX + p0) * 7 + d;  // y=1
#pragma unroll
        for (int px = 0; px < 4; px++) {
            float lo, hi;
            unpack2(acc[px][j], lo, hi);
            outr[base0 + 7 * px] = lo;
            outr[base1 + 7 * px] = hi;
        }
    }
}

extern "C" void kernel_launch(void* const* d_in, const int* in_sizes, int n_in,
                              void* d_out, int out_size)
{
    const float* feat = (const float*)d_in[0];
    const float* Wc   = (const float*)d_in[1];
    const float* bc   = (const float*)d_in[2];
    const float* Wr   = (const float*)d_in[3];
    const float* br   = (const float*)d_in[4];
    float* out = (float*)d_out;

    const int smem_bytes = (CIN * NOUT + NOUT) * (int)sizeof(float);  // 73920 B
    cudaFuncSetAttribute(proposal_kernel,
                         cudaFuncAttributeMaxDynamicSharedMemorySize, smem_bytes);

    const int threads = 128;                       // 4 warps: 2 pixel-groups x 2 out-halves
    const int blocks  = TOTAL_PIX / 256;           // 550, exact
    proposal_kernel<<<blocks, threads, smem_bytes>>>(feat, Wc, bc, Wr, br, out);
}

// round 6
// speedup vs baseline: 3.1077x; 3.1077x over previous
#include <cuda_runtime.h>

#define NOUT 48
#define CIN 384
#define NPIX 35200       // 200*176
#define NB 4
#define TOTAL_PIX 140800 // = 550 * 256

extern __shared__ float s_buf[];   // ws[CIN][48] (tf32-rounded), then bs[48]

__device__ __forceinline__ float to_tf32(float x) {
    float r;
    asm("cvt.rna.tf32.f32 %0, %1;" : "=f"(r) : "f"(x));
    return r;
}

// D (=C in-place) 16x8 fp32 += A(16x8 tf32, row) * B(8x8 tf32, col)
__device__ __forceinline__ void mma_tf32(float c[4], const unsigned a[4], const unsigned b[2]) {
    asm("mma.sync.aligned.m16n8k8.row.col.f32.tf32.tf32.f32 "
        "{%0,%1,%2,%3}, {%4,%5,%6,%7}, {%8,%9}, {%0,%1,%2,%3};"
        : "+f"(c[0]), "+f"(c[1]), "+f"(c[2]), "+f"(c[3])
        : "r"(a[0]), "r"(a[1]), "r"(a[2]), "r"(a[3]), "r"(b[0]), "r"(b[1]));
}

__global__ __launch_bounds__(256, 2)
void proposal_kernel(const float* __restrict__ feat,
                     const float* __restrict__ Wc,
                     const float* __restrict__ bc,
                     const float* __restrict__ Wr,
                     const float* __restrict__ br,
                     float* __restrict__ out)
{
    float* ws = s_buf;               // ws[c*48 + o] = tf32(W[o][c])
    float* bs = s_buf + CIN * NOUT;

    const int tid = threadIdx.x;

    for (int i = tid; i < CIN * NOUT; i += blockDim.x) {
        const int c = i / NOUT;
        const int o = i % NOUT;
        ws[i] = to_tf32((o < 6) ? Wc[o * CIN + c] : Wr[(o - 6) * CIN + c]);
    }
    if (tid < NOUT) bs[tid] = (tid < 6) ? bc[tid] : br[tid - 6];
    __syncthreads();

    const int lane = tid & 31;
    const int warp = tid >> 5;          // 8 warps; warp owns 32 pixels
    const int gid  = lane >> 2;         // 0..7
    const int tg   = lane & 3;          // 0..3

    // 4 pixel rows this thread touches: mt in {0,1}, row-half h in {0,1}
    // row index within warp tile: mt*16 + h*8 + gid
    const int m_base = blockIdx.x * 256 + warp * 32;
    int   rb[4];   // batch per row
    int   rp[4];   // pixel-within-batch per row
    const float* rptr[4];
#pragma unroll
    for (int i = 0; i < 4; i++) {
        const int mt = i >> 1, h = i & 1;
        const int g = m_base + mt * 16 + h * 8 + gid;
        rb[i] = g / NPIX;
        rp[i] = g % NPIX;
        rptr[i] = feat + (long)rb[i] * CIN * NPIX + rp[i];
    }

    // acc[mt][nt][0..3]: c0=(row h0, col even) c1=(h0, odd) c2=(h1, even) c3=(h1, odd)
    // columns: n = 8*nt + 2*tg (+1)
    float acc[2][6][4];
#pragma unroll
    for (int mt = 0; mt < 2; mt++)
#pragma unroll
        for (int nt = 0; nt < 6; nt++) {
            const float be = bs[8 * nt + 2 * tg];
            const float bo = bs[8 * nt + 2 * tg + 1];
            acc[mt][nt][0] = be; acc[mt][nt][1] = bo;
            acc[mt][nt][2] = be; acc[mt][nt][3] = bo;
        }

    const unsigned* wsu = (const unsigned*)ws;
    const long kstep0 = (long)tg * NPIX;          // channel offset for a0/a1
    const long kstep4 = (long)(tg + 4) * NPIX;    // channel offset for a2/a3

#pragma unroll 4
    for (int k0 = 0; k0 < CIN; k0 += 8) {
        const long kb = (long)k0 * NPIX;
        // A fragments: a0 (row h0, k=tg), a1 (row h1, k=tg), a2 (h0, k=tg+4), a3 (h1, k=tg+4)
        unsigned a[2][4];
#pragma unroll
        for (int mt = 0; mt < 2; mt++) {
            a[mt][0] = __float_as_uint(to_tf32(rptr[2 * mt + 0][kb + kstep0]));
            a[mt][1] = __float_as_uint(to_tf32(rptr[2 * mt + 1][kb + kstep0]));
            a[mt][2] = __float_as_uint(to_tf32(rptr[2 * mt + 0][kb + kstep4]));
            a[mt][3] = __float_as_uint(to_tf32(rptr[2 * mt + 1][kb + kstep4]));
        }
        const int w0 = (k0 + tg) * NOUT;          // row k=tg
        const int w1 = (k0 + tg + 4) * NOUT;      // row k=tg+4
#pragma unroll
        for (int nt = 0; nt < 6; nt++) {
            unsigned b[2];
            b[0] = wsu[w0 + 8 * nt + gid];        // (k=tg,   n=8nt+gid)
            b[1] = wsu[w1 + 8 * nt + gid];        // (k=tg+4, n=8nt+gid)
            mma_tf32(acc[0][nt], a[0], b);
            mma_tf32(acc[1][nt], a[1], b);
        }
    }

    // ================= epilogue =================
    // thread's channel pair per nt: Q = 4*nt + tg covers outputs (2Q, 2Q+1)
    float* outr = out + (long)NB * 6 * NPIX;
#pragma unroll
    for (int mt = 0; mt < 2; mt++) {
#pragma unroll
        for (int h = 0; h < 2; h++) {
            const int i = 2 * mt + h;
            const int b = rb[i];
            const int p = rp[i];
#pragma unroll
            for (int nt = 0; nt < 6; nt++) {
                const float ve = acc[mt][nt][2 * h + 0];  // even channel (2Q)
                const float vo = acc[mt][nt][2 * h + 1];  // odd  channel (2Q+1)
                const int Q = 4 * nt + tg;
                if (Q < 3) {
                    // cls: out[(b*6 + o)*NPIX + p]
                    out[((long)b * 6 + 2 * Q + 0) * NPIX + p] = ve;
                    out[((long)b * 6 + 2 * Q + 1) * NPIX + p] = vo;
                } else {
                    // reg: (B, 3, 2, ny, nx, 7); even->y=0, odd->y=1
                    const int r  = Q - 3;
                    const int c3 = r / 7;
                    const int d  = r % 7;
                    outr[((((long)b * 3 + c3) * 2 + 0) * NPIX + p) * 7 + d] = ve;
                    outr[((((long)b * 3 + c3) * 2 + 1) * NPIX + p) * 7 + d] = vo;
                }
            }
        }
    }
}

extern "C" void kernel_launch(void* const* d_in, const int* in_sizes, int n_in,
                              void* d_out, int out_size)
{
    const float* feat = (const float*)d_in[0];
    const float* Wc   = (const float*)d_in[1];
    const float* bc   = (const float*)d_in[2];
    const float* Wr   = (const float*)d_in[3];
    const float* br   = (const float*)d_in[4];
    float* out = (float*)d_out;

    const int smem_bytes = (CIN * NOUT + NOUT) * (int)sizeof(float);  // 73920 B
    cudaFuncSetAttribute(proposal_kernel,
                         cudaFuncAttributeMaxDynamicSharedMemorySize, smem_bytes);

    const int threads = 256;                 // 8 warps x 32 pixels = 256 pixels/block
    const int blocks  = TOTAL_PIX / 256;     // 550, exact
    proposal_kernel<<<blocks, threads, smem_bytes>>>(feat, Wc, bc, Wr, br, out);
}